// round 6
// baseline (speedup 1.0000x reference)
#include <cuda_runtime.h>
#include <cstdint>
#include <cstddef>

// Problem constants (B=4, H=16, L=2048, D=64)
#define BATCH 4
#define HEADS 16
#define BH    (BATCH * HEADS)   // 64
#define SEQ   2048
#define DIM   64
#define TEMP_INV 0.125f         // 1/8

// Tiling
#define BM 64
#define BN 64
#define QPITCH 68   // smem pitch (multiple of 4 for float4 alignment)

// Scratch: per-row sum of exp (64*2048 rows)
__device__ float g_rowsum[BH * SEQ];

// -----------------------------------------------------------------------------
// Kernel 1: E = exp(Q K^T / 8) with mask, write E to attn buffer, rowsum -> g_rowsum
// grid: (SEQ/BM, BH), block: 256 (16x16 logical)
// -----------------------------------------------------------------------------
__global__ __launch_bounds__(256)
void attn_scores_kernel(const float* __restrict__ q,
                        const float* __restrict__ k,
                        const unsigned char* __restrict__ mask,
                        float* __restrict__ attn)
{
    const int bh = blockIdx.y;
    const int b  = bh >> 4;
    const int m0 = blockIdx.x * BM;
    const int tid = threadIdx.x;
    const int tx = tid & 15;        // 0..15 -> 4 cols each
    const int ty = tid >> 4;        // 0..15 -> 4 rows each

    __shared__ float Qt[DIM][QPITCH];   // Qt[d][r]
    __shared__ float Kt[DIM][QPITCH];   // Kt[d][c]

    // Load Q tile transposed: Qt[d][r] = Q[bh, m0+r, d]
    {
        const float* qbase = q + ((size_t)bh * SEQ + m0) * DIM;
        const int d = tid & 63;
        #pragma unroll
        for (int r = tid >> 6; r < BM; r += 4) {
            Qt[d][r] = qbase[(size_t)r * DIM + d];
        }
    }

    float acc_rs[4] = {0.f, 0.f, 0.f, 0.f};

    for (int n0 = 0; n0 < SEQ; n0 += BN) {
        __syncthreads();
        // Load K tile transposed: Kt[d][c] = K[bh, n0+c, d]
        {
            const float* kbase = k + ((size_t)bh * SEQ + n0) * DIM;
            const int d = tid & 63;
            #pragma unroll
            for (int c = tid >> 6; c < BN; c += 4) {
                Kt[d][c] = kbase[(size_t)c * DIM + d];
            }
        }
        __syncthreads();

        float acc[4][4] = {};
        #pragma unroll 16
        for (int d = 0; d < DIM; d++) {
            float4 a = *(const float4*)&Qt[d][ty * 4];
            float4 bb = *(const float4*)&Kt[d][tx * 4];
            acc[0][0] += a.x * bb.x; acc[0][1] += a.x * bb.y; acc[0][2] += a.x * bb.z; acc[0][3] += a.x * bb.w;
            acc[1][0] += a.y * bb.x; acc[1][1] += a.y * bb.y; acc[1][2] += a.y * bb.z; acc[1][3] += a.y * bb.w;
            acc[2][0] += a.z * bb.x; acc[2][1] += a.z * bb.y; acc[2][2] += a.z * bb.z; acc[2][3] += a.z * bb.w;
            acc[3][0] += a.w * bb.x; acc[3][1] += a.w * bb.y; acc[3][2] += a.w * bb.z; acc[3][3] += a.w * bb.w;
        }

        // Epilogue: exp + mask + store E + rowsum accumulate
        #pragma unroll
        for (int i = 0; i < 4; i++) {
            const int row = m0 + ty * 4 + i;
            const int col = n0 + tx * 4;
            uchar4 m4 = *(const uchar4*)&mask[((size_t)b * SEQ + row) * SEQ + col];
            float e0 = m4.x ? 0.f : __expf(acc[i][0] * TEMP_INV);
            float e1 = m4.y ? 0.f : __expf(acc[i][1] * TEMP_INV);
            float e2 = m4.z ? 0.f : __expf(acc[i][2] * TEMP_INV);
            float e3 = m4.w ? 0.f : __expf(acc[i][3] * TEMP_INV);
            float4 ev = make_float4(e0, e1, e2, e3);
            *(float4*)&attn[((size_t)bh * SEQ + row) * SEQ + col] = ev;
            acc_rs[i] += (e0 + e1) + (e2 + e3);
        }
    }

    // Reduce rowsums across tx (lane bits 0..3 carry tx)
    #pragma unroll
    for (int i = 0; i < 4; i++) {
        float v = acc_rs[i];
        v += __shfl_xor_sync(0xffffffff, v, 1);
        v += __shfl_xor_sync(0xffffffff, v, 2);
        v += __shfl_xor_sync(0xffffffff, v, 4);
        v += __shfl_xor_sync(0xffffffff, v, 8);
        if (tx == 0) {
            g_rowsum[(size_t)bh * SEQ + m0 + ty * 4 + i] = v;
        }
    }
}

// -----------------------------------------------------------------------------
// Kernel 2: P = E / rowsum (written back into attn), O = P V -> res
// grid: (SEQ/BM, BH), block: 256
// -----------------------------------------------------------------------------
__global__ __launch_bounds__(256)
void attn_pv_kernel(const float* __restrict__ v,
                    float* __restrict__ attn,
                    float* __restrict__ res)
{
    const int bh = blockIdx.y;
    const int m0 = blockIdx.x * BM;
    const int tid = threadIdx.x;
    const int tx = tid & 15;
    const int ty = tid >> 4;

    __shared__ float Pt[BN][QPITCH];  // Pt[c][r]
    __shared__ float Vs[BN][DIM];     // Vs[c][d]
    __shared__ float rinv_s[BM];

    if (tid < BM) {
        rinv_s[tid] = 1.0f / g_rowsum[(size_t)bh * SEQ + m0 + tid];
    }
    __syncthreads();

    float rinv[4];
    #pragma unroll
    for (int i = 0; i < 4; i++) rinv[i] = rinv_s[ty * 4 + i];

    float o[4][4] = {};

    for (int n0 = 0; n0 < SEQ; n0 += BN) {
        __syncthreads();
        // Load V tile: Vs[c][d]
        {
            const float* vbase = v + ((size_t)bh * SEQ + n0) * DIM;
            const int d = tid & 63;
            #pragma unroll
            for (int c = tid >> 6; c < BN; c += 4) {
                Vs[c][d] = vbase[(size_t)c * DIM + d];
            }
        }
        // Load E tile, normalize, write P back, stage transposed in smem
        #pragma unroll
        for (int i = 0; i < 4; i++) {
            const int row = m0 + ty * 4 + i;
            const int col = n0 + tx * 4;
            float* ap = &attn[((size_t)bh * SEQ + row) * SEQ + col];
            float4 e4 = *(const float4*)ap;
            e4.x *= rinv[i]; e4.y *= rinv[i]; e4.z *= rinv[i]; e4.w *= rinv[i];
            *(float4*)ap = e4;
            const int r = ty * 4 + i;
            Pt[tx * 4 + 0][r] = e4.x;
            Pt[tx * 4 + 1][r] = e4.y;
            Pt[tx * 4 + 2][r] = e4.z;
            Pt[tx * 4 + 3][r] = e4.w;
        }
        __syncthreads();

        #pragma unroll 16
        for (int c = 0; c < BN; c++) {
            float4 a = *(const float4*)&Pt[c][ty * 4];
            float4 bb = *(const float4*)&Vs[c][tx * 4];
            o[0][0] += a.x * bb.x; o[0][1] += a.x * bb.y; o[0][2] += a.x * bb.z; o[0][3] += a.x * bb.w;
            o[1][0] += a.y * bb.x; o[1][1] += a.y * bb.y; o[1][2] += a.y * bb.z; o[1][3] += a.y * bb.w;
            o[2][0] += a.z * bb.x; o[2][1] += a.z * bb.y; o[2][2] += a.z * bb.z; o[2][3] += a.z * bb.w;
            o[3][0] += a.w * bb.x; o[3][1] += a.w * bb.y; o[3][2] += a.w * bb.z; o[3][3] += a.w * bb.w;
        }
    }

    // Write O tile: res[bh, row, d]
    #pragma unroll
    for (int i = 0; i < 4; i++) {
        const int row = m0 + ty * 4 + i;
        float4 ov = make_float4(o[i][0], o[i][1], o[i][2], o[i][3]);
        *(float4*)&res[((size_t)bh * SEQ + row) * DIM + tx * 4] = ov;
    }
}

// -----------------------------------------------------------------------------
// Launch
// Inputs (metadata order): query f32 [4,16,2048,64], key f32, value f32,
//                          mask bool [4,2048,2048]
// Output: res [4,16,2048,64] (8,388,608 f32) followed by
//         attention [4,16,2048,2048] (268,435,456 f32)
// -----------------------------------------------------------------------------
extern "C" void kernel_launch(void* const* d_in, const int* in_sizes, int n_in,
                              void* d_out, int out_size)
{
    const float* q = (const float*)d_in[0];
    const float* k = (const float*)d_in[1];
    const float* v = (const float*)d_in[2];
    const unsigned char* mask = (const unsigned char*)d_in[3];

    float* res  = (float*)d_out;
    float* attn = (float*)d_out + (size_t)BH * SEQ * DIM;  // after res

    dim3 grid(SEQ / BM, BH);
    dim3 block(256);

    attn_scores_kernel<<<grid, block>>>(q, k, mask, attn);
    attn_pv_kernel<<<grid, block>>>(v, attn, res);
}

// round 11
// speedup vs baseline: 1.0013x; 1.0013x over previous
#include <cuda_runtime.h>
#include <cstdint>
#include <cstddef>

// Problem constants (B=4, H=16, L=2048, D=64)
#define BATCH 4
#define HEADS 16
#define BH    (BATCH * HEADS)   // 64
#define SEQ   2048
#define DIM   64
#define TEMP_INV 0.125f         // 1/8

// Tiling
#define BM 64
#define BN 64
#define QPITCH 68   // smem pitch (multiple of 4 for float4 alignment)

// Scratch: per-row sum of exp (64*2048 rows)
__device__ float g_rowsum[BH * SEQ];

// -----------------------------------------------------------------------------
// Kernel 1: E = exp(Q K^T / 8) with mask, write E to attn buffer, rowsum -> g_rowsum
// grid: (SEQ/BM, BH), block: 256 (16x16 logical)
// -----------------------------------------------------------------------------
__global__ __launch_bounds__(256)
void attn_scores_kernel(const float* __restrict__ q,
                        const float* __restrict__ k,
                        const unsigned char* __restrict__ mask,
                        float* __restrict__ attn)
{
    const int bh = blockIdx.y;
    const int b  = bh >> 4;
    const int m0 = blockIdx.x * BM;
    const int tid = threadIdx.x;
    const int tx = tid & 15;        // 0..15 -> 4 cols each
    const int ty = tid >> 4;        // 0..15 -> 4 rows each

    __shared__ float Qt[DIM][QPITCH];   // Qt[d][r]
    __shared__ float Kt[DIM][QPITCH];   // Kt[d][c]

    // Load Q tile transposed: Qt[d][r] = Q[bh, m0+r, d]
    {
        const float* qbase = q + ((size_t)bh * SEQ + m0) * DIM;
        const int d = tid & 63;
        #pragma unroll
        for (int r = tid >> 6; r < BM; r += 4) {
            Qt[d][r] = qbase[(size_t)r * DIM + d];
        }
    }

    float acc_rs[4] = {0.f, 0.f, 0.f, 0.f};

    for (int n0 = 0; n0 < SEQ; n0 += BN) {
        __syncthreads();
        // Load K tile transposed: Kt[d][c] = K[bh, n0+c, d]
        {
            const float* kbase = k + ((size_t)bh * SEQ + n0) * DIM;
            const int d = tid & 63;
            #pragma unroll
            for (int c = tid >> 6; c < BN; c += 4) {
                Kt[d][c] = kbase[(size_t)c * DIM + d];
            }
        }
        __syncthreads();

        float acc[4][4] = {};
        #pragma unroll 16
        for (int d = 0; d < DIM; d++) {
            float4 a = *(const float4*)&Qt[d][ty * 4];
            float4 bb = *(const float4*)&Kt[d][tx * 4];
            acc[0][0] += a.x * bb.x; acc[0][1] += a.x * bb.y; acc[0][2] += a.x * bb.z; acc[0][3] += a.x * bb.w;
            acc[1][0] += a.y * bb.x; acc[1][1] += a.y * bb.y; acc[1][2] += a.y * bb.z; acc[1][3] += a.y * bb.w;
            acc[2][0] += a.z * bb.x; acc[2][1] += a.z * bb.y; acc[2][2] += a.z * bb.z; acc[2][3] += a.z * bb.w;
            acc[3][0] += a.w * bb.x; acc[3][1] += a.w * bb.y; acc[3][2] += a.w * bb.z; acc[3][3] += a.w * bb.w;
        }

        // Epilogue: exp + mask + store E + rowsum accumulate
        #pragma unroll
        for (int i = 0; i < 4; i++) {
            const int row = m0 + ty * 4 + i;
            const int col = n0 + tx * 4;
            uchar4 m4 = *(const uchar4*)&mask[((size_t)b * SEQ + row) * SEQ + col];
            float e0 = m4.x ? 0.f : __expf(acc[i][0] * TEMP_INV);
            float e1 = m4.y ? 0.f : __expf(acc[i][1] * TEMP_INV);
            float e2 = m4.z ? 0.f : __expf(acc[i][2] * TEMP_INV);
            float e3 = m4.w ? 0.f : __expf(acc[i][3] * TEMP_INV);
            float4 ev = make_float4(e0, e1, e2, e3);
            *(float4*)&attn[((size_t)bh * SEQ + row) * SEQ + col] = ev;
            acc_rs[i] += (e0 + e1) + (e2 + e3);
        }
    }

    // Reduce rowsums across tx (lane bits 0..3 carry tx)
    #pragma unroll
    for (int i = 0; i < 4; i++) {
        float v = acc_rs[i];
        v += __shfl_xor_sync(0xffffffff, v, 1);
        v += __shfl_xor_sync(0xffffffff, v, 2);
        v += __shfl_xor_sync(0xffffffff, v, 4);
        v += __shfl_xor_sync(0xffffffff, v, 8);
        if (tx == 0) {
            g_rowsum[(size_t)bh * SEQ + m0 + ty * 4 + i] = v;
        }
    }
}

// -----------------------------------------------------------------------------
// Kernel 2: P = E / rowsum (written back into attn), O = P V -> res
// grid: (SEQ/BM, BH), block: 256
// -----------------------------------------------------------------------------
__global__ __launch_bounds__(256)
void attn_pv_kernel(const float* __restrict__ v,
                    float* __restrict__ attn,
                    float* __restrict__ res)
{
    const int bh = blockIdx.y;
    const int m0 = blockIdx.x * BM;
    const int tid = threadIdx.x;
    const int tx = tid & 15;
    const int ty = tid >> 4;

    __shared__ float Pt[BN][QPITCH];  // Pt[c][r]
    __shared__ float Vs[BN][DIM];     // Vs[c][d]
    __shared__ float rinv_s[BM];

    if (tid < BM) {
        rinv_s[tid] = 1.0f / g_rowsum[(size_t)bh * SEQ + m0 + tid];
    }
    __syncthreads();

    float rinv[4];
    #pragma unroll
    for (int i = 0; i < 4; i++) rinv[i] = rinv_s[ty * 4 + i];

    float o[4][4] = {};

    for (int n0 = 0; n0 < SEQ; n0 += BN) {
        __syncthreads();
        // Load V tile: Vs[c][d]
        {
            const float* vbase = v + ((size_t)bh * SEQ + n0) * DIM;
            const int d = tid & 63;
            #pragma unroll
            for (int c = tid >> 6; c < BN; c += 4) {
                Vs[c][d] = vbase[(size_t)c * DIM + d];
            }
        }
        // Load E tile, normalize, write P back, stage transposed in smem
        #pragma unroll
        for (int i = 0; i < 4; i++) {
            const int row = m0 + ty * 4 + i;
            const int col = n0 + tx * 4;
            float* ap = &attn[((size_t)bh * SEQ + row) * SEQ + col];
            float4 e4 = *(const float4*)ap;
            e4.x *= rinv[i]; e4.y *= rinv[i]; e4.z *= rinv[i]; e4.w *= rinv[i];
            *(float4*)ap = e4;
            const int r = ty * 4 + i;
            Pt[tx * 4 + 0][r] = e4.x;
            Pt[tx * 4 + 1][r] = e4.y;
            Pt[tx * 4 + 2][r] = e4.z;
            Pt[tx * 4 + 3][r] = e4.w;
        }
        __syncthreads();

        #pragma unroll 16
        for (int c = 0; c < BN; c++) {
            float4 a = *(const float4*)&Pt[c][ty * 4];
            float4 bb = *(const float4*)&Vs[c][tx * 4];
            o[0][0] += a.x * bb.x; o[0][1] += a.x * bb.y; o[0][2] += a.x * bb.z; o[0][3] += a.x * bb.w;
            o[1][0] += a.y * bb.x; o[1][1] += a.y * bb.y; o[1][2] += a.y * bb.z; o[1][3] += a.y * bb.w;
            o[2][0] += a.z * bb.x; o[2][1] += a.z * bb.y; o[2][2] += a.z * bb.z; o[2][3] += a.z * bb.w;
            o[3][0] += a.w * bb.x; o[3][1] += a.w * bb.y; o[3][2] += a.w * bb.z; o[3][3] += a.w * bb.w;
        }
    }

    // Write O tile: res[bh, row, d]
    #pragma unroll
    for (int i = 0; i < 4; i++) {
        const int row = m0 + ty * 4 + i;
        float4 ov = make_float4(o[i][0], o[i][1], o[i][2], o[i][3]);
        *(float4*)&res[((size_t)bh * SEQ + row) * DIM + tx * 4] = ov;
    }
}

// -----------------------------------------------------------------------------
// Launch
// Inputs (metadata order): query f32 [4,16,2048,64], key f32, value f32,
//                          mask bool [4,2048,2048]
// Output: res [4,16,2048,64] (8,388,608 f32) followed by
//         attention [4,16,2048,2048] (268,435,456 f32)
// -----------------------------------------------------------------------------
extern "C" void kernel_launch(void* const* d_in, const int* in_sizes, int n_in,
                              void* d_out, int out_size)
{
    const float* q = (const float*)d_in[0];
    const float* k = (const float*)d_in[1];
    const float* v = (const float*)d_in[2];
    const unsigned char* mask = (const unsigned char*)d_in[3];

    float* res  = (float*)d_out;
    float* attn = (float*)d_out + (size_t)BH * SEQ * DIM;  // after res

    dim3 grid(SEQ / BM, BH);
    dim3 block(256);

    attn_scores_kernel<<<grid, block>>>(q, k, mask, attn);
    attn_pv_kernel<<<grid, block>>>(v, attn, res);
}